// round 1
// baseline (speedup 1.0000x reference)
#include <cuda_runtime.h>
#include <math.h>

// ---------------------------------------------------------------------------
// Problem constants (reference: N=100000 nodes, E=3200000 edges, 256 graphs)
// ---------------------------------------------------------------------------
#define N_MAX   100000
#define E_MAX   3200000
#define G_MAX   256
#define F1      96      // layer1/2 out
#define F3      30      // layer3 out
#define NCLS    10

// ---------------------------------------------------------------------------
// Device scratch (static globals: allocation-free per harness rules)
// ---------------------------------------------------------------------------
__device__ int   g_is64;
__device__ int   g_src[E_MAX];
__device__ int   g_dst[E_MAX];
__device__ int   g_bat[N_MAX];
__device__ float g_deg[N_MAX];
__device__ float g_dis[N_MAX];
__device__ float g_norm[E_MAX];
__device__ float g_bufA[N_MAX * F1];   // xw (linear output, pre-norm)
__device__ float g_bufB[N_MAX * F1];   // accumulator layer 1 / layer 3
__device__ float g_bufC[N_MAX * F1];   // accumulator layer 2
__device__ float g_pool[G_MAX * F3];
__device__ float g_cnt[G_MAX];

// ---------------------------------------------------------------------------
// 0) Detect whether edge_index / batch are int64 or int32.
//    If int64 (values < 2^31, little-endian), every odd 32-bit word is 0.
//    If int32, odd words are random node ids in [0,100000) -> OR is nonzero.
// ---------------------------------------------------------------------------
__global__ void detect_kernel(const unsigned int* __restrict__ raw) {
    __shared__ unsigned int sh[256];
    int t = threadIdx.x;
    unsigned int v = 0;
    for (int i = t; i < 1024; i += 256) v |= raw[2 * i + 1];
    sh[t] = v;
    __syncthreads();
    for (int s = 128; s > 0; s >>= 1) {
        if (t < s) sh[t] |= sh[t + s];
        __syncthreads();
    }
    if (t == 0) g_is64 = (sh[0] == 0u) ? 1 : 0;
}

// ---------------------------------------------------------------------------
// 1) Convert indices to int32 scratch + zero-init accumulators.
// ---------------------------------------------------------------------------
__global__ void convert_kernel(const void* __restrict__ ei,
                               const void* __restrict__ bat,
                               int E, int N) {
    int idx = blockIdx.x * blockDim.x + threadIdx.x;
    int is64 = g_is64;
    if (idx < E) {
        if (is64) {
            const long long* p = (const long long*)ei;
            g_src[idx] = (int)p[idx];
            g_dst[idx] = (int)p[E + idx];
        } else {
            const int* p = (const int*)ei;
            g_src[idx] = p[idx];
            g_dst[idx] = p[E + idx];
        }
    }
    if (idx < N) {
        if (is64) g_bat[idx] = (int)((const long long*)bat)[idx];
        else      g_bat[idx] = ((const int*)bat)[idx];
        g_deg[idx] = 0.0f;
    }
    if (idx < G_MAX * F3) g_pool[idx] = 0.0f;
    if (idx < G_MAX)      g_cnt[idx]  = 0.0f;
}

// ---------------------------------------------------------------------------
// 2) Weighted in-degree: deg[dst] += |w|
// ---------------------------------------------------------------------------
__global__ void deg_kernel(const float* __restrict__ ew, int E) {
    int i = blockIdx.x * blockDim.x + threadIdx.x;
    if (i < E) atomicAdd(&g_deg[g_dst[i]], fabsf(ew[i]));
}

// 3) dis = rsqrt(deg + 1)
__global__ void dis_kernel(int N) {
    int i = blockIdx.x * blockDim.x + threadIdx.x;
    if (i < N) g_dis[i] = rsqrtf(g_deg[i] + 1.0f);
}

// 4) per-edge norm: dis[src] * |w| * dis[dst]
__global__ void norm_kernel(const float* __restrict__ ew, int E) {
    int i = blockIdx.x * blockDim.x + threadIdx.x;
    if (i < E) g_norm[i] = g_dis[g_src[i]] * fabsf(ew[i]) * g_dis[g_dst[i]];
}

// ---------------------------------------------------------------------------
// 5) Tiled GEMM: xw = act(in) @ W;  acc = dis^2 * xw + b  (self-loop + bias
//    pre-initialized so the edge scatter can atomically add on top).
//    Block covers BN=NT*TN nodes x FOUT cols, 256 threads, reg tile TN x TC.
// ---------------------------------------------------------------------------
template<int FIN, int FOUT, int CT, int TC, int NT, int TN, bool RELU_IN>
__global__ __launch_bounds__(256) void gemm_kernel(
    const float* __restrict__ in, const float* __restrict__ W,
    const float* __restrict__ b,
    float* __restrict__ xw_out, float* __restrict__ acc_out, int N)
{
    constexpr int BN = NT * TN;                 // nodes per block (64)
    constexpr int KC = 32;                      // k-chunk
    constexpr int FP = (FOUT < 32) ? 32 : FOUT; // padded ws width
    __shared__ float xs[BN][KC + 1];
    __shared__ float ws[KC][FP];

    const int n0 = blockIdx.x * BN;
    const int t  = threadIdx.x;
    const int ct = t % CT;          // column group
    const int nt = t / CT;          // node group

    float acc[TN][TC];
#pragma unroll
    for (int i = 0; i < TN; i++)
#pragma unroll
        for (int j = 0; j < TC; j++) acc[i][j] = 0.0f;

    for (int k0 = 0; k0 < FIN; k0 += KC) {
        // cooperative load of x tile (coalesced 128B rows)
        for (int i = t; i < BN * KC; i += 256) {
            int r = i / KC, c = i % KC;
            int n = n0 + r;
            float v = (n < N) ? in[n * FIN + k0 + c] : 0.0f;
            if (RELU_IN) v = fmaxf(v, 0.0f);
            xs[r][c] = v;
        }
        // cooperative load of W tile
        for (int i = t; i < KC * FP; i += 256) {
            int r = i / FP, c = i % FP;
            ws[r][c] = (c < FOUT) ? W[(k0 + r) * FOUT + c] : 0.0f;
        }
        __syncthreads();

#pragma unroll
        for (int k = 0; k < KC; k++) {
            float xr[TN], wr[TC];
#pragma unroll
            for (int i = 0; i < TN; i++) xr[i] = xs[nt * TN + i][k];
#pragma unroll
            for (int j = 0; j < TC; j++) wr[j] = ws[k][ct * TC + j];
#pragma unroll
            for (int i = 0; i < TN; i++)
#pragma unroll
                for (int j = 0; j < TC; j++) acc[i][j] += xr[i] * wr[j];
        }
        __syncthreads();
    }

#pragma unroll
    for (int i = 0; i < TN; i++) {
        int n = n0 + nt * TN + i;
        if (n >= N) continue;
        float d  = g_dis[n];
        float sn = d * d;
#pragma unroll
        for (int j = 0; j < TC; j++) {
            int c = ct * TC + j;
            if (c >= FOUT) continue;
            float v = acc[i][j];
            xw_out[n * FOUT + c]  = v;
            acc_out[n * FOUT + c] = sn * v + b[c];
        }
    }
}

// ---------------------------------------------------------------------------
// 6) Edge scatter: acc[dst] += norm[e] * xw[src]   (warp per edge)
// ---------------------------------------------------------------------------
template<int FOUT>
__global__ __launch_bounds__(256) void scatter_kernel(
    const float* __restrict__ xw, float* __restrict__ acc, int E)
{
    const int lane   = threadIdx.x & 31;
    const int warp   = (blockIdx.x * blockDim.x + threadIdx.x) >> 5;
    const int nwarps = (gridDim.x * blockDim.x) >> 5;
    for (int e = warp; e < E; e += nwarps) {
        const int   s  = g_src[e];
        const int   d  = g_dst[e];
        const float ne = g_norm[e];
        const long long sb = (long long)s * FOUT;
        const long long db = (long long)d * FOUT;
#pragma unroll
        for (int f = lane; f < FOUT; f += 32)
            atomicAdd(&acc[db + f], ne * __ldg(&xw[sb + f]));
    }
}

// ---------------------------------------------------------------------------
// 7) Global mean pool (sums via atomics; batch-sorted but atomics are cheap)
// ---------------------------------------------------------------------------
__global__ void pool_kernel(const float* __restrict__ h, int N) {
    int tid = blockIdx.x * blockDim.x + threadIdx.x;
    int n = tid >> 5;
    int f = tid & 31;
    if (n >= N) return;
    int g = g_bat[n];
    if (f < F3) {
        atomicAdd(&g_pool[g * F3 + f], fmaxf(h[n * F3 + f], 0.0f));
    } else if (f == 31) {
        atomicAdd(&g_cnt[g], 1.0f);
    }
}

// ---------------------------------------------------------------------------
// 8) Final classifier + softmax: one thread per graph
// ---------------------------------------------------------------------------
__global__ void final_kernel(const float* __restrict__ Wf,
                             const float* __restrict__ bf,
                             float* __restrict__ out) {
    int g = threadIdx.x;
    if (g >= G_MAX) return;
    float cnt = fmaxf(g_cnt[g], 1.0f);
    float p[F3];
#pragma unroll
    for (int j = 0; j < F3; j++) p[j] = g_pool[g * F3 + j] / cnt;
    float lo[NCLS];
    float m = -1e30f;
#pragma unroll
    for (int k = 0; k < NCLS; k++) {
        float s = bf[k];
#pragma unroll
        for (int j = 0; j < F3; j++) s += p[j] * Wf[j * NCLS + k];
        lo[k] = s;
        m = fmaxf(m, s);
    }
    float sum = 0.0f;
#pragma unroll
    for (int k = 0; k < NCLS; k++) { lo[k] = expf(lo[k] - m); sum += lo[k]; }
    float inv = 1.0f / sum;
#pragma unroll
    for (int k = 0; k < NCLS; k++) out[g * NCLS + k] = lo[k] * inv;
}

// ---------------------------------------------------------------------------
// Launch
// ---------------------------------------------------------------------------
extern "C" void kernel_launch(void* const* d_in, const int* in_sizes, int n_in,
                              void* d_out, int out_size) {
    const float* x   = (const float*)d_in[0];
    const void*  ei  = d_in[1];
    const float* ew  = (const float*)d_in[2];
    const void*  bat = d_in[3];
    const float* W1  = (const float*)d_in[4];
    const float* b1  = (const float*)d_in[5];
    const float* W2  = (const float*)d_in[6];
    const float* b2  = (const float*)d_in[7];
    const float* W3  = (const float*)d_in[8];
    const float* b3  = (const float*)d_in[9];
    const float* Wf  = (const float*)d_in[10];
    const float* bf  = (const float*)d_in[11];
    float* out = (float*)d_out;

    const int E = in_sizes[2];   // edge_weight element count = #edges
    const int N = in_sizes[3];   // batch element count = #nodes

    float *pA, *pB, *pC;
    cudaGetSymbolAddress((void**)&pA, g_bufA);
    cudaGetSymbolAddress((void**)&pB, g_bufB);
    cudaGetSymbolAddress((void**)&pC, g_bufC);

    const int TB = 256;
    const int gE = (E + TB - 1) / TB;
    const int gN = (N + TB - 1) / TB;
    const int gGemm = (N + 63) / 64;
    const int gScatter = 16384;
    const int gPool = (N * 32 + TB - 1) / TB;

    detect_kernel<<<1, 256>>>((const unsigned int*)ei);
    convert_kernel<<<gE, TB>>>(ei, bat, E, N);
    deg_kernel<<<gE, TB>>>(ew, E);
    dis_kernel<<<gN, TB>>>(N);
    norm_kernel<<<gE, TB>>>(ew, E);

    // Layer 1: 128 -> 96 (no input relu)
    gemm_kernel<128, 96, 16, 6, 16, 4, false><<<gGemm, TB>>>(x, W1, b1, pA, pB, N);
    scatter_kernel<96><<<gScatter, TB>>>(pA, pB, E);

    // Layer 2: 96 -> 96 (relu on input)
    gemm_kernel<96, 96, 16, 6, 16, 4, true><<<gGemm, TB>>>(pB, W2, b2, pA, pC, N);
    scatter_kernel<96><<<gScatter, TB>>>(pA, pC, E);

    // Layer 3: 96 -> 30 (relu on input)
    gemm_kernel<96, 30, 8, 4, 32, 2, true><<<gGemm, TB>>>(pC, W3, b3, pA, pB, N);
    scatter_kernel<30><<<gScatter, TB>>>(pA, pB, E);

    // Mean pool (with relu) + classifier + softmax
    pool_kernel<<<gPool, TB>>>(pB, N);
    final_kernel<<<1, 256>>>(Wf, bf, out);

    (void)n_in; (void)out_size;
}

// round 2
// speedup vs baseline: 1.3437x; 1.3437x over previous
#include <cuda_runtime.h>
#include <math.h>

// ---------------------------------------------------------------------------
// Problem constants (reference: N=100000 nodes, E=3200000 edges, 256 graphs)
// ---------------------------------------------------------------------------
#define N_MAX   100000
#define E_MAX   3200000
#define G_MAX   256
#define F1      96      // layer1/2 out
#define F3      30      // layer3 out
#define NCLS    10

// ---------------------------------------------------------------------------
// Device scratch (static globals: allocation-free per harness rules)
// ---------------------------------------------------------------------------
__device__ int   g_is64;
__device__ int   g_src[E_MAX];
__device__ int   g_dst[E_MAX];
__device__ int   g_bat[N_MAX];
__device__ float g_deg[N_MAX];
__device__ float g_dis[N_MAX];
__device__ float g_norm[E_MAX];
// CSR (indexed by dst)
__device__ int   g_hist[N_MAX];
__device__ int   g_rowptr[N_MAX + 1];
__device__ int   g_wofs[N_MAX];
__device__ int   g_col[E_MAX];     // src per CSR slot
__device__ float g_val[E_MAX];     // norm per CSR slot
// feature buffers
__device__ float g_bufA[N_MAX * F1];   // xw (linear output, pre-aggregation)
__device__ float g_bufB[N_MAX * F1];   // layer output ping
__device__ float g_bufC[N_MAX * F1];   // layer output pong
__device__ float g_pool[G_MAX * F3];
__device__ float g_cnt[G_MAX];

// ---------------------------------------------------------------------------
// 0) Detect int64 vs int32 indices (odd 32-bit words all zero => int64)
// ---------------------------------------------------------------------------
__global__ void detect_kernel(const unsigned int* __restrict__ raw) {
    __shared__ unsigned int sh[256];
    int t = threadIdx.x;
    unsigned int v = 0;
    for (int i = t; i < 1024; i += 256) v |= raw[2 * i + 1];
    sh[t] = v;
    __syncthreads();
    for (int s = 128; s > 0; s >>= 1) {
        if (t < s) sh[t] |= sh[t + s];
        __syncthreads();
    }
    if (t == 0) g_is64 = (sh[0] == 0u) ? 1 : 0;
}

// ---------------------------------------------------------------------------
// 1) Convert indices to int32 + zero-init deg/hist/pool
// ---------------------------------------------------------------------------
__global__ void convert_kernel(const void* __restrict__ ei,
                               const void* __restrict__ bat,
                               int E, int N) {
    int idx = blockIdx.x * blockDim.x + threadIdx.x;
    int is64 = g_is64;
    if (idx < E) {
        if (is64) {
            const long long* p = (const long long*)ei;
            g_src[idx] = (int)p[idx];
            g_dst[idx] = (int)p[E + idx];
        } else {
            const int* p = (const int*)ei;
            g_src[idx] = p[idx];
            g_dst[idx] = p[E + idx];
        }
    }
    if (idx < N) {
        if (is64) g_bat[idx] = (int)((const long long*)bat)[idx];
        else      g_bat[idx] = ((const int*)bat)[idx];
        g_deg[idx]  = 0.0f;
        g_hist[idx] = 0;
    }
    if (idx < G_MAX * F3) g_pool[idx] = 0.0f;
    if (idx < G_MAX)      g_cnt[idx]  = 0.0f;
}

// ---------------------------------------------------------------------------
// 2) Fused weighted in-degree + dst histogram
// ---------------------------------------------------------------------------
__global__ void deghist_kernel(const float* __restrict__ ew, int E) {
    int i = blockIdx.x * blockDim.x + threadIdx.x;
    if (i < E) {
        int d = g_dst[i];
        atomicAdd(&g_deg[d], fabsf(ew[i]));
        atomicAdd(&g_hist[d], 1);
    }
}

// 3) dis = rsqrt(deg + 1)
__global__ void dis_kernel(int N) {
    int i = blockIdx.x * blockDim.x + threadIdx.x;
    if (i < N) g_dis[i] = rsqrtf(g_deg[i] + 1.0f);
}

// 4) per-edge norm
__global__ void norm_kernel(const float* __restrict__ ew, int E) {
    int i = blockIdx.x * blockDim.x + threadIdx.x;
    if (i < E) g_norm[i] = g_dis[g_src[i]] * fabsf(ew[i]) * g_dis[g_dst[i]];
}

// ---------------------------------------------------------------------------
// 5) Single-block exclusive scan of hist -> rowptr (+ working copy wofs)
// ---------------------------------------------------------------------------
__global__ __launch_bounds__(1024) void scan_kernel(int N) {
    __shared__ int sh[1024];
    int t = threadIdx.x;
    int chunk = (N + 1023) >> 10;
    int lo = t * chunk;
    int hi = lo + chunk; if (hi > N) hi = N; if (lo > N) lo = N;
    int s = 0;
    for (int i = lo; i < hi; i++) s += g_hist[i];
    sh[t] = s;
    __syncthreads();
    // Hillis-Steele inclusive scan
    for (int off = 1; off < 1024; off <<= 1) {
        int v = (t >= off) ? sh[t - off] : 0;
        __syncthreads();
        sh[t] += v;
        __syncthreads();
    }
    int run = (t == 0) ? 0 : sh[t - 1];
    for (int i = lo; i < hi; i++) {
        g_rowptr[i] = run;
        g_wofs[i]   = run;
        run += g_hist[i];
    }
    if (hi == N) g_rowptr[N] = run;   // empty-range threads also write total E
}

// ---------------------------------------------------------------------------
// 6) Edge placement into CSR slots
// ---------------------------------------------------------------------------
__global__ void place_kernel(int E) {
    int i = blockIdx.x * blockDim.x + threadIdx.x;
    if (i < E) {
        int d = g_dst[i];
        int p = atomicAdd(&g_wofs[d], 1);
        g_col[p] = g_src[i];
        g_val[p] = g_norm[i];
    }
}

// ---------------------------------------------------------------------------
// 7) Tiled GEMM: xw = act(in) @ W   (self-loop/bias moved to gather epilogue)
// ---------------------------------------------------------------------------
template<int FIN, int FOUT, int CT, int TC, int NT, int TN, bool RELU_IN>
__global__ __launch_bounds__(256) void gemm_kernel(
    const float* __restrict__ in, const float* __restrict__ W,
    float* __restrict__ xw_out, int N)
{
    constexpr int BN = NT * TN;
    constexpr int KC = 32;
    constexpr int FP = (FOUT < 32) ? 32 : FOUT;
    __shared__ float xs[BN][KC + 1];
    __shared__ float ws[KC][FP];

    const int n0 = blockIdx.x * BN;
    const int t  = threadIdx.x;
    const int ct = t % CT;
    const int nt = t / CT;

    float acc[TN][TC];
#pragma unroll
    for (int i = 0; i < TN; i++)
#pragma unroll
        for (int j = 0; j < TC; j++) acc[i][j] = 0.0f;

    for (int k0 = 0; k0 < FIN; k0 += KC) {
        for (int i = t; i < BN * KC; i += 256) {
            int r = i / KC, c = i % KC;
            int n = n0 + r;
            float v = (n < N) ? in[(long long)n * FIN + k0 + c] : 0.0f;
            if (RELU_IN) v = fmaxf(v, 0.0f);
            xs[r][c] = v;
        }
        for (int i = t; i < KC * FP; i += 256) {
            int r = i / FP, c = i % FP;
            ws[r][c] = (c < FOUT) ? W[(k0 + r) * FOUT + c] : 0.0f;
        }
        __syncthreads();

#pragma unroll
        for (int k = 0; k < KC; k++) {
            float xr[TN], wr[TC];
#pragma unroll
            for (int i = 0; i < TN; i++) xr[i] = xs[nt * TN + i][k];
#pragma unroll
            for (int j = 0; j < TC; j++) wr[j] = ws[k][ct * TC + j];
#pragma unroll
            for (int i = 0; i < TN; i++)
#pragma unroll
                for (int j = 0; j < TC; j++) acc[i][j] += xr[i] * wr[j];
        }
        __syncthreads();
    }

#pragma unroll
    for (int i = 0; i < TN; i++) {
        int n = n0 + nt * TN + i;
        if (n >= N) continue;
#pragma unroll
        for (int j = 0; j < TC; j++) {
            int c = ct * TC + j;
            if (c < FOUT) xw_out[(long long)n * FOUT + c] = acc[i][j];
        }
    }
}

// ---------------------------------------------------------------------------
// 8) Pull aggregation: warp per node.
//    out[n] = sum_{e in CSR row n} val[e] * xw[col[e]] + dis[n]^2 * xw[n] + b
//    Lanes cooperatively load 32 (col,val) pairs coalesced, broadcast via
//    shfl; each lane accumulates NF features at stride 32 (coalesced 128B).
// ---------------------------------------------------------------------------
template<int FOUT, int NF>
__global__ __launch_bounds__(256) void gather_kernel(
    const float* __restrict__ xw, const float* __restrict__ b,
    float* __restrict__ out, int N)
{
    const int lane = threadIdx.x & 31;
    const int n = (blockIdx.x * blockDim.x + threadIdx.x) >> 5;
    if (n >= N) return;

    const int beg = g_rowptr[n];
    const int end = g_rowptr[n + 1];

    float acc[NF];
#pragma unroll
    for (int j = 0; j < NF; j++) acc[j] = 0.0f;

    for (int e0 = beg; e0 < end; e0 += 32) {
        const int m = end - e0;
        int   c_r = 0;
        float v_r = 0.0f;
        if (lane < m) { c_r = g_col[e0 + lane]; v_r = g_val[e0 + lane]; }
        const int cnt = (m < 32) ? m : 32;
        for (int k = 0; k < cnt; k++) {
            const int   c  = __shfl_sync(0xffffffffu, c_r, k);
            const float wv = __shfl_sync(0xffffffffu, v_r, k);
            const float* row = xw + (long long)c * FOUT;
#pragma unroll
            for (int j = 0; j < NF; j++)
                acc[j] += wv * __ldg(&row[lane + 32 * j]);
        }
    }

    const float d  = g_dis[n];
    const float sn = d * d;
    const float* xr = xw + (long long)n * FOUT;
#pragma unroll
    for (int j = 0; j < NF; j++) {
        const int f = lane + 32 * j;
        if (f < FOUT)
            out[(long long)n * FOUT + f] = acc[j] + sn * xr[f] + b[f];
    }
}

// ---------------------------------------------------------------------------
// 9) Global mean pool (with fused relu on layer-3 output)
// ---------------------------------------------------------------------------
__global__ void pool_kernel(const float* __restrict__ h, int N) {
    int tid = blockIdx.x * blockDim.x + threadIdx.x;
    int n = tid >> 5;
    int f = tid & 31;
    if (n >= N) return;
    int g = g_bat[n];
    if (f < F3) {
        atomicAdd(&g_pool[g * F3 + f], fmaxf(h[n * F3 + f], 0.0f));
    } else if (f == 31) {
        atomicAdd(&g_cnt[g], 1.0f);
    }
}

// ---------------------------------------------------------------------------
// 10) Final classifier + softmax
// ---------------------------------------------------------------------------
__global__ void final_kernel(const float* __restrict__ Wf,
                             const float* __restrict__ bf,
                             float* __restrict__ out) {
    int g = threadIdx.x;
    if (g >= G_MAX) return;
    float cnt = fmaxf(g_cnt[g], 1.0f);
    float p[F3];
#pragma unroll
    for (int j = 0; j < F3; j++) p[j] = g_pool[g * F3 + j] / cnt;
    float lo[NCLS];
    float m = -1e30f;
#pragma unroll
    for (int k = 0; k < NCLS; k++) {
        float s = bf[k];
#pragma unroll
        for (int j = 0; j < F3; j++) s += p[j] * Wf[j * NCLS + k];
        lo[k] = s;
        m = fmaxf(m, s);
    }
    float sum = 0.0f;
#pragma unroll
    for (int k = 0; k < NCLS; k++) { lo[k] = expf(lo[k] - m); sum += lo[k]; }
    float inv = 1.0f / sum;
#pragma unroll
    for (int k = 0; k < NCLS; k++) out[g * NCLS + k] = lo[k] * inv;
}

// ---------------------------------------------------------------------------
// Launch
// ---------------------------------------------------------------------------
extern "C" void kernel_launch(void* const* d_in, const int* in_sizes, int n_in,
                              void* d_out, int out_size) {
    const float* x   = (const float*)d_in[0];
    const void*  ei  = d_in[1];
    const float* ew  = (const float*)d_in[2];
    const void*  bat = d_in[3];
    const float* W1  = (const float*)d_in[4];
    const float* b1  = (const float*)d_in[5];
    const float* W2  = (const float*)d_in[6];
    const float* b2  = (const float*)d_in[7];
    const float* W3  = (const float*)d_in[8];
    const float* b3  = (const float*)d_in[9];
    const float* Wf  = (const float*)d_in[10];
    const float* bf  = (const float*)d_in[11];
    float* out = (float*)d_out;

    const int E = in_sizes[2];   // edge_weight element count = #edges
    const int N = in_sizes[3];   // batch element count = #nodes

    float *pA, *pB, *pC;
    cudaGetSymbolAddress((void**)&pA, g_bufA);
    cudaGetSymbolAddress((void**)&pB, g_bufB);
    cudaGetSymbolAddress((void**)&pC, g_bufC);

    const int TB = 256;
    const int gE = (E + TB - 1) / TB;
    const int gN = (N + TB - 1) / TB;
    const int gGemm = (N + 63) / 64;
    const int gGather = (N * 32 + TB - 1) / TB;   // warp per node
    const int gPool = (N * 32 + TB - 1) / TB;

    // preprocessing + CSR build
    detect_kernel<<<1, 256>>>((const unsigned int*)ei);
    convert_kernel<<<gE, TB>>>(ei, bat, E, N);
    deghist_kernel<<<gE, TB>>>(ew, E);
    dis_kernel<<<gN, TB>>>(N);
    norm_kernel<<<gE, TB>>>(ew, E);
    scan_kernel<<<1, 1024>>>(N);
    place_kernel<<<gE, TB>>>(E);

    // Layer 1: 128 -> 96
    gemm_kernel<128, 96, 16, 6, 16, 4, false><<<gGemm, TB>>>(x, W1, pA, N);
    gather_kernel<96, 3><<<gGather, TB>>>(pA, b1, pB, N);

    // Layer 2: 96 -> 96 (relu fused into gemm load)
    gemm_kernel<96, 96, 16, 6, 16, 4, true><<<gGemm, TB>>>(pB, W2, pA, N);
    gather_kernel<96, 3><<<gGather, TB>>>(pA, b2, pC, N);

    // Layer 3: 96 -> 30
    gemm_kernel<96, 30, 8, 4, 32, 2, true><<<gGemm, TB>>>(pC, W3, pA, N);
    gather_kernel<30, 1><<<gGather, TB>>>(pA, b3, pB, N);

    // Mean pool (with relu) + classifier + softmax
    pool_kernel<<<gPool, TB>>>(pB, N);
    final_kernel<<<1, 256>>>(Wf, bf, out);

    (void)n_in; (void)out_size;
}

// round 3
// speedup vs baseline: 1.3697x; 1.0193x over previous
#include <cuda_runtime.h>
#include <cuda_fp16.h>
#include <math.h>

// ---------------------------------------------------------------------------
// Problem constants (reference: N=100000 nodes, E=3200000 edges, 256 graphs)
// ---------------------------------------------------------------------------
#define N_MAX   100000
#define E_MAX   3200000
#define G_MAX   256
#define F1      96
#define F3      30
#define NCLS    10

// ---------------------------------------------------------------------------
// Device scratch (static globals: allocation-free per harness rules)
// ---------------------------------------------------------------------------
__device__ int    g_is64;
__device__ int    g_src[E_MAX];
__device__ int    g_dst[E_MAX];
__device__ int    g_bat[N_MAX];
__device__ float  g_deg[N_MAX];
__device__ float  g_dis[N_MAX];
__device__ int    g_hist[N_MAX];
__device__ int    g_rowptr[N_MAX + 1];
__device__ int    g_wofs[N_MAX];
__device__ int2   g_csr[E_MAX];        // {src, float_as_int(norm)} per CSR slot
__device__ __half g_xw[N_MAX * F1];    // fp16 linear output (pre-aggregation)
__device__ float  g_bufB[N_MAX * F1];  // layer output ping (fp32)
__device__ float  g_bufC[N_MAX * F1];  // layer output pong (fp32)
__device__ float  g_pool[G_MAX * F3];
__device__ float  g_cnt[G_MAX];

// ---------------------------------------------------------------------------
// 0) Detect int64 vs int32 indices (odd 32-bit words all zero => int64)
// ---------------------------------------------------------------------------
__global__ void detect_kernel(const unsigned int* __restrict__ raw) {
    __shared__ unsigned int sh[256];
    int t = threadIdx.x;
    unsigned int v = 0;
    for (int i = t; i < 1024; i += 256) v |= raw[2 * i + 1];
    sh[t] = v;
    __syncthreads();
    for (int s = 128; s > 0; s >>= 1) {
        if (t < s) sh[t] |= sh[t + s];
        __syncthreads();
    }
    if (t == 0) g_is64 = (sh[0] == 0u) ? 1 : 0;
}

// ---------------------------------------------------------------------------
// 1) Zero-init accumulators (must precede fused convert+deghist atomics)
// ---------------------------------------------------------------------------
__global__ void zero_kernel(int N) {
    int i = blockIdx.x * blockDim.x + threadIdx.x;
    if (i < N) { g_deg[i] = 0.0f; g_hist[i] = 0; }
    if (i < G_MAX * F3) g_pool[i] = 0.0f;
    if (i < G_MAX)      g_cnt[i]  = 0.0f;
}

// ---------------------------------------------------------------------------
// 2) Fused: index conversion + weighted in-degree + dst histogram + batch
// ---------------------------------------------------------------------------
__global__ void convert_deghist_kernel(const void* __restrict__ ei,
                                       const void* __restrict__ bat,
                                       const float* __restrict__ ew,
                                       int E, int N) {
    int idx = blockIdx.x * blockDim.x + threadIdx.x;
    int is64 = g_is64;
    if (idx < E) {
        int s, d;
        if (is64) {
            const long long* p = (const long long*)ei;
            s = (int)p[idx];
            d = (int)p[E + idx];
        } else {
            const int* p = (const int*)ei;
            s = p[idx];
            d = p[E + idx];
        }
        g_src[idx] = s;
        g_dst[idx] = d;
        atomicAdd(&g_deg[d], fabsf(ew[idx]));
        atomicAdd(&g_hist[d], 1);
    }
    if (idx < N) {
        if (is64) g_bat[idx] = (int)((const long long*)bat)[idx];
        else      g_bat[idx] = ((const int*)bat)[idx];
    }
}

// 3) dis = rsqrt(deg + 1)
__global__ void dis_kernel(int N) {
    int i = blockIdx.x * blockDim.x + threadIdx.x;
    if (i < N) g_dis[i] = rsqrtf(g_deg[i] + 1.0f);
}

// ---------------------------------------------------------------------------
// 4) Single-block exclusive scan of hist -> rowptr (+ working copy wofs)
// ---------------------------------------------------------------------------
__global__ __launch_bounds__(1024) void scan_kernel(int N) {
    __shared__ int sh[1024];
    int t = threadIdx.x;
    int chunk = (N + 1023) >> 10;
    int lo = t * chunk;
    int hi = lo + chunk; if (hi > N) hi = N; if (lo > N) lo = N;
    int s = 0;
    for (int i = lo; i < hi; i++) s += g_hist[i];
    sh[t] = s;
    __syncthreads();
    for (int off = 1; off < 1024; off <<= 1) {
        int v = (t >= off) ? sh[t - off] : 0;
        __syncthreads();
        sh[t] += v;
        __syncthreads();
    }
    int run = (t == 0) ? 0 : sh[t - 1];
    for (int i = lo; i < hi; i++) {
        g_rowptr[i] = run;
        g_wofs[i]   = run;
        run += g_hist[i];
    }
    if (hi == N) g_rowptr[N] = run;
}

// ---------------------------------------------------------------------------
// 5) Fused: per-edge norm + CSR placement (packed 8B write)
// ---------------------------------------------------------------------------
__global__ void normplace_kernel(const float* __restrict__ ew, int E) {
    int i = blockIdx.x * blockDim.x + threadIdx.x;
    if (i < E) {
        int   s = g_src[i];
        int   d = g_dst[i];
        float nv = g_dis[s] * fabsf(ew[i]) * g_dis[d];
        int p = atomicAdd(&g_wofs[d], 1);
        g_csr[p] = make_int2(s, __float_as_int(nv));
    }
}

// ---------------------------------------------------------------------------
// 6) Tiled GEMM: xw(fp16) = act(in) @ W
//    256 threads, BN nodes x FOUT cols, register tile TN x TC.
// ---------------------------------------------------------------------------
template<int FIN, int FOUT, int CT, int TC, int NT, int TN, bool RELU_IN>
__global__ __launch_bounds__(256) void gemm_kernel(
    const float* __restrict__ in, const float* __restrict__ W,
    __half* __restrict__ xw_out, int N)
{
    constexpr int BN = NT * TN;                 // 128
    constexpr int KC = 32;
    constexpr int FP = (FOUT < 32) ? 32 : FOUT;
    __shared__ float xs[BN][KC + 1];
    __shared__ float ws[KC][FP];

    const int n0 = blockIdx.x * BN;
    const int t  = threadIdx.x;
    const int ct = t % CT;
    const int nt = t / CT;

    float acc[TN][TC];
#pragma unroll
    for (int i = 0; i < TN; i++)
#pragma unroll
        for (int j = 0; j < TC; j++) acc[i][j] = 0.0f;

    for (int k0 = 0; k0 < FIN; k0 += KC) {
        // x tile: float4 loads, scalar STS into padded smem
        constexpr int V = KC / 4;               // float4 per row (8)
        for (int i = t; i < BN * V; i += 256) {
            int r = i / V, c4 = i % V;
            int n = n0 + r;
            float4 v = make_float4(0.f, 0.f, 0.f, 0.f);
            if (n < N)
                v = *(const float4*)(in + (long long)n * FIN + k0 + c4 * 4);
            if (RELU_IN) {
                v.x = fmaxf(v.x, 0.f); v.y = fmaxf(v.y, 0.f);
                v.z = fmaxf(v.z, 0.f); v.w = fmaxf(v.w, 0.f);
            }
            xs[r][c4 * 4 + 0] = v.x;
            xs[r][c4 * 4 + 1] = v.y;
            xs[r][c4 * 4 + 2] = v.z;
            xs[r][c4 * 4 + 3] = v.w;
        }
        // W tile
        for (int i = t; i < KC * FP; i += 256) {
            int r = i / FP, c = i % FP;
            ws[r][c] = (c < FOUT) ? W[(k0 + r) * FOUT + c] : 0.0f;
        }
        __syncthreads();

#pragma unroll
        for (int k = 0; k < KC; k++) {
            float xr[TN], wr[TC];
#pragma unroll
            for (int i = 0; i < TN; i++) xr[i] = xs[nt * TN + i][k];
#pragma unroll
            for (int j = 0; j < TC; j++) wr[j] = ws[k][ct * TC + j];
#pragma unroll
            for (int i = 0; i < TN; i++)
#pragma unroll
                for (int j = 0; j < TC; j++) acc[i][j] += xr[i] * wr[j];
        }
        __syncthreads();
    }

#pragma unroll
    for (int i = 0; i < TN; i++) {
        int n = n0 + nt * TN + i;
        if (n >= N) continue;
#pragma unroll
        for (int j = 0; j < TC; j++) {
            int c = ct * TC + j;
            if (c < FOUT)
                xw_out[(long long)n * FOUT + c] = __float2half_rn(acc[i][j]);
        }
    }
}

// ---------------------------------------------------------------------------
// 7) Pull aggregation (warp per node, fp16 rows, fp32 accumulate):
//    out[n] = sum_e val[e]*xw[col[e]] + dis[n]^2 * xw[n] + b
// ---------------------------------------------------------------------------
template<int FOUT, int NF>
__global__ __launch_bounds__(256) void gather_kernel(
    const __half* __restrict__ xw, const float* __restrict__ b,
    float* __restrict__ out, int N)
{
    const int lane = threadIdx.x & 31;
    const int n = (blockIdx.x * blockDim.x + threadIdx.x) >> 5;
    if (n >= N) return;

    const int beg = g_rowptr[n];
    const int end = g_rowptr[n + 1];

    float acc[NF];
#pragma unroll
    for (int j = 0; j < NF; j++) acc[j] = 0.0f;

    for (int e0 = beg; e0 < end; e0 += 32) {
        const int m = end - e0;
        int2 cv = make_int2(0, 0);
        if (lane < m) cv = g_csr[e0 + lane];
        const int cnt = (m < 32) ? m : 32;
        for (int k = 0; k < cnt; k++) {
            const int   c  = __shfl_sync(0xffffffffu, cv.x, k);
            const float wv = __int_as_float(__shfl_sync(0xffffffffu, cv.y, k));
            const __half* row = xw + (long long)c * FOUT;
#pragma unroll
            for (int j = 0; j < NF; j++)
                acc[j] += wv * __half2float(__ldg(&row[lane + 32 * j]));
        }
    }

    const float d  = g_dis[n];
    const float sn = d * d;
    const __half* xr = xw + (long long)n * FOUT;
#pragma unroll
    for (int j = 0; j < NF; j++) {
        const int f = lane + 32 * j;
        if (f < FOUT)
            out[(long long)n * FOUT + f] =
                acc[j] + sn * __half2float(xr[f]) + b[f];
    }
}

// ---------------------------------------------------------------------------
// 8) Global mean pool (fused relu on layer-3 output)
// ---------------------------------------------------------------------------
__global__ void pool_kernel(const float* __restrict__ h, int N) {
    int tid = blockIdx.x * blockDim.x + threadIdx.x;
    int n = tid >> 5;
    int f = tid & 31;
    if (n >= N) return;
    int g = g_bat[n];
    if (f < F3) {
        atomicAdd(&g_pool[g * F3 + f], fmaxf(h[n * F3 + f], 0.0f));
    } else if (f == 31) {
        atomicAdd(&g_cnt[g], 1.0f);
    }
}

// ---------------------------------------------------------------------------
// 9) Final classifier + softmax
// ---------------------------------------------------------------------------
__global__ void final_kernel(const float* __restrict__ Wf,
                             const float* __restrict__ bf,
                             float* __restrict__ out) {
    int g = threadIdx.x;
    if (g >= G_MAX) return;
    float cnt = fmaxf(g_cnt[g], 1.0f);
    float p[F3];
#pragma unroll
    for (int j = 0; j < F3; j++) p[j] = g_pool[g * F3 + j] / cnt;
    float lo[NCLS];
    float m = -1e30f;
#pragma unroll
    for (int k = 0; k < NCLS; k++) {
        float s = bf[k];
#pragma unroll
        for (int j = 0; j < F3; j++) s += p[j] * Wf[j * NCLS + k];
        lo[k] = s;
        m = fmaxf(m, s);
    }
    float sum = 0.0f;
#pragma unroll
    for (int k = 0; k < NCLS; k++) { lo[k] = expf(lo[k] - m); sum += lo[k]; }
    float inv = 1.0f / sum;
#pragma unroll
    for (int k = 0; k < NCLS; k++) out[g * NCLS + k] = lo[k] * inv;
}

// ---------------------------------------------------------------------------
// Launch
// ---------------------------------------------------------------------------
extern "C" void kernel_launch(void* const* d_in, const int* in_sizes, int n_in,
                              void* d_out, int out_size) {
    const float* x   = (const float*)d_in[0];
    const void*  ei  = d_in[1];
    const float* ew  = (const float*)d_in[2];
    const void*  bat = d_in[3];
    const float* W1  = (const float*)d_in[4];
    const float* b1  = (const float*)d_in[5];
    const float* W2  = (const float*)d_in[6];
    const float* b2  = (const float*)d_in[7];
    const float* W3  = (const float*)d_in[8];
    const float* b3  = (const float*)d_in[9];
    const float* Wf  = (const float*)d_in[10];
    const float* bf  = (const float*)d_in[11];
    float* out = (float*)d_out;

    const int E = in_sizes[2];
    const int N = in_sizes[3];

    __half *pXW;
    float *pB, *pC;
    cudaGetSymbolAddress((void**)&pXW, g_xw);
    cudaGetSymbolAddress((void**)&pB,  g_bufB);
    cudaGetSymbolAddress((void**)&pC,  g_bufC);

    const int TB = 256;
    const int gE = (E + TB - 1) / TB;
    const int gN = (N + TB - 1) / TB;
    const int gGemm = (N + 127) / 128;
    const int gGather = (N * 32 + TB - 1) / TB;
    const int gPool = (N * 32 + TB - 1) / TB;

    // preprocessing + CSR build (2 edge passes total)
    detect_kernel<<<1, 256>>>((const unsigned int*)ei);
    zero_kernel<<<gN, TB>>>(N);
    convert_deghist_kernel<<<gE, TB>>>(ei, bat, ew, E, N);
    dis_kernel<<<gN, TB>>>(N);
    scan_kernel<<<1, 1024>>>(N);
    normplace_kernel<<<gE, TB>>>(ew, E);

    // Layer 1: 128 -> 96
    gemm_kernel<128, 96, 16, 6, 16, 8, false><<<gGemm, TB>>>(x, W1, pXW, N);
    gather_kernel<96, 3><<<gGather, TB>>>(pXW, b1, pB, N);

    // Layer 2: 96 -> 96 (relu fused into gemm load)
    gemm_kernel<96, 96, 16, 6, 16, 8, true><<<gGemm, TB>>>(pB, W2, pXW, N);
    gather_kernel<96, 3><<<gGather, TB>>>(pXW, b2, pC, N);

    // Layer 3: 96 -> 30
    gemm_kernel<96, 30, 8, 4, 32, 4, true><<<gGemm, TB>>>(pC, W3, pXW, N);
    gather_kernel<30, 1><<<gGather, TB>>>(pXW, b3, pB, N);

    // Mean pool (with relu) + classifier + softmax
    pool_kernel<<<gPool, TB>>>(pB, N);
    final_kernel<<<1, 256>>>(Wf, bf, out);

    (void)n_in; (void)out_size;
}

// round 4
// speedup vs baseline: 1.6312x; 1.1910x over previous
#include <cuda_runtime.h>
#include <cuda_fp16.h>
#include <math.h>

#define N_MAX   100000
#define E_MAX   3200000
#define G_MAX   256
#define F3      30
#define NCLS    10

// Weight offsets in fp16 scratch: W1 128x96, W2 96x96, W3 96x30 (raw)
#define WOFF1   0
#define WOFF2   (128*96)
#define WOFF3   (128*96 + 96*96)
#define WTOT    (128*96 + 96*96 + 96*30)

// ---------------------------------------------------------------------------
// Device scratch
// ---------------------------------------------------------------------------
__device__ int    g_is64;
__device__ int    g_src[E_MAX];
__device__ int    g_dst[E_MAX];
__device__ int    g_bat[N_MAX];
__device__ float  g_dis[N_MAX];
__device__ int    g_hist[N_MAX];
__device__ int    g_rowptr[N_MAX + 1];
__device__ int    g_wofs[N_MAX];
__device__ int2   g_csr[E_MAX];          // {src, float_as_int(|w|)}
__device__ __half g_wh[WTOT];            // fp16 weights
__device__ __half g_xw[N_MAX * 96];      // xw' = dis[n]*xw[n]  (fp16)
__device__ float  g_bufB[N_MAX * 96];
__device__ float  g_bufC[N_MAX * 96];
__device__ float  g_pool[G_MAX * F3];
__device__ float  g_cnt[G_MAX];

// ---------------------------------------------------------------------------
// helpers
// ---------------------------------------------------------------------------
__device__ __forceinline__ unsigned smem_u32(const void* p) {
    return (unsigned)__cvta_generic_to_shared(p);
}
__device__ __forceinline__ void ldsm_x4(unsigned* r, unsigned addr) {
    asm volatile("ldmatrix.sync.aligned.m8n8.x4.shared.b16 {%0,%1,%2,%3}, [%4];"
                 : "=r"(r[0]), "=r"(r[1]), "=r"(r[2]), "=r"(r[3]) : "r"(addr));
}
__device__ __forceinline__ void ldsm_x4t(unsigned* r, unsigned addr) {
    asm volatile("ldmatrix.sync.aligned.m8n8.x4.trans.shared.b16 {%0,%1,%2,%3}, [%4];"
                 : "=r"(r[0]), "=r"(r[1]), "=r"(r[2]), "=r"(r[3]) : "r"(addr));
}
__device__ __forceinline__ void mma16816(float* d, const unsigned* a, const unsigned* b) {
    asm volatile(
        "mma.sync.aligned.m16n8k16.row.col.f32.f16.f16.f32 "
        "{%0,%1,%2,%3}, {%4,%5,%6,%7}, {%8,%9}, {%0,%1,%2,%3};"
        : "+f"(d[0]), "+f"(d[1]), "+f"(d[2]), "+f"(d[3])
        : "r"(a[0]), "r"(a[1]), "r"(a[2]), "r"(a[3]), "r"(b[0]), "r"(b[1]));
}

// ---------------------------------------------------------------------------
// 0) int64/int32 detect
// ---------------------------------------------------------------------------
__global__ void detect_kernel(const unsigned* __restrict__ raw) {
    __shared__ unsigned sh[256];
    int t = threadIdx.x;
    unsigned v = 0;
    for (int i = t; i < 1024; i += 256) v |= raw[2 * i + 1];
    sh[t] = v;
    __syncthreads();
    for (int s = 128; s > 0; s >>= 1) {
        if (t < s) sh[t] |= sh[t + s];
        __syncthreads();
    }
    if (t == 0) g_is64 = (sh[0] == 0u) ? 1 : 0;
}

// 1) zero-init
__global__ void zero_kernel(int N) {
    int i = blockIdx.x * blockDim.x + threadIdx.x;
    if (i < N) g_hist[i] = 0;
    if (i < G_MAX * F3) g_pool[i] = 0.0f;
    if (i < G_MAX)      g_cnt[i]  = 0.0f;
}

// 2) convert indices + dst histogram + batch
__global__ void convert_hist_kernel(const void* __restrict__ ei,
                                    const void* __restrict__ bat,
                                    int E, int N) {
    int idx = blockIdx.x * blockDim.x + threadIdx.x;
    int is64 = g_is64;
    if (idx < E) {
        int s, d;
        if (is64) {
            const long long* p = (const long long*)ei;
            s = (int)p[idx];
            d = (int)p[E + idx];
        } else {
            const int* p = (const int*)ei;
            s = p[idx];
            d = p[E + idx];
        }
        g_src[idx] = s;
        g_dst[idx] = d;
        atomicAdd(&g_hist[d], 1);
    }
    if (idx < N) {
        if (is64) g_bat[idx] = (int)((const long long*)bat)[idx];
        else      g_bat[idx] = ((const int*)bat)[idx];
    }
}

// 3) weights fp32 -> fp16
__global__ void wconv_kernel(const float* __restrict__ W1,
                             const float* __restrict__ W2,
                             const float* __restrict__ W3) {
    int i = blockIdx.x * blockDim.x + threadIdx.x;
    if (i < WOFF2)      g_wh[i] = __float2half(W1[i]);
    else if (i < WOFF3) g_wh[i] = __float2half(W2[i - WOFF2]);
    else if (i < WTOT)  g_wh[i] = __float2half(W3[i - WOFF3]);
}

// 4) single-block scan: hist -> rowptr, wofs
__global__ __launch_bounds__(1024) void scan_kernel(int N) {
    __shared__ int sh[1024];
    int t = threadIdx.x;
    int chunk = (N + 1023) >> 10;
    int lo = t * chunk;
    int hi = lo + chunk; if (hi > N) hi = N; if (lo > N) lo = N;
    int s = 0;
    for (int i = lo; i < hi; i++) s += g_hist[i];
    sh[t] = s;
    __syncthreads();
    for (int off = 1; off < 1024; off <<= 1) {
        int v = (t >= off) ? sh[t - off] : 0;
        __syncthreads();
        sh[t] += v;
        __syncthreads();
    }
    int run = (t == 0) ? 0 : sh[t - 1];
    for (int i = lo; i < hi; i++) {
        g_rowptr[i] = run;
        g_wofs[i]   = run;
        run += g_hist[i];
    }
    if (hi == N) g_rowptr[N] = run;
}

// 5) CSR placement: {src, |w|}
__global__ void place_kernel(const float* __restrict__ ew, int E) {
    int i = blockIdx.x * blockDim.x + threadIdx.x;
    if (i < E) {
        int d = g_dst[i];
        int p = atomicAdd(&g_wofs[d], 1);
        g_csr[p] = make_int2(g_src[i], __float_as_int(fabsf(ew[i])));
    }
}

// 6) degree + dis from CSR (coalesced, no atomics): dis = rsqrt(sum|w| + 1)
__global__ void degdis_kernel(int N) {
    int lane = threadIdx.x & 31;
    int n = (blockIdx.x * blockDim.x + threadIdx.x) >> 5;
    if (n >= N) return;
    int beg = g_rowptr[n], end = g_rowptr[n + 1];
    float s = 0.0f;
    for (int e = beg + lane; e < end; e += 32)
        s += __int_as_float(g_csr[e].y);
#pragma unroll
    for (int o = 16; o; o >>= 1) s += __shfl_xor_sync(0xffffffffu, s, o);
    if (lane == 0) g_dis[n] = rsqrtf(s + 1.0f);
}

// ---------------------------------------------------------------------------
// 7) HMMA GEMM: xw'(fp16) = dis[n] * (act(in) @ W)
//    block = 128 rows x FOUTP cols; 8 warps (4m x 2n); warp tile 32 x FOUTP/2.
// ---------------------------------------------------------------------------
template<int FIN, int FOUT, int FOUTP, bool RELU>
__global__ __launch_bounds__(256) void gemm_hmma(
    const float* __restrict__ in, const __half* __restrict__ Wh,
    __half* __restrict__ xw, int N)
{
    constexpr int KC  = 32;
    constexpr int LDA = KC + 8;        // 40 halves -> conflict-free ldmatrix
    constexpr int LDB = FOUTP + 8;     // 104 / 40 -> conflict-free
    constexpr int NT  = FOUTP / 16;    // n8-tiles per warp (6 or 2)

    __shared__ __half As[128 * LDA];
    __shared__ __half Bs[KC * LDB];

    const int t    = threadIdx.x;
    const int lane = t & 31;
    const int wid  = t >> 5;
    const int wm   = wid >> 1;         // 0..3
    const int wn   = wid & 1;          // 0..1
    const int rowblk = blockIdx.x * 128;

    float acc[2][NT][4];
#pragma unroll
    for (int mt = 0; mt < 2; mt++)
#pragma unroll
        for (int nt = 0; nt < NT; nt++)
#pragma unroll
            for (int q = 0; q < 4; q++) acc[mt][nt][q] = 0.0f;

    for (int k0 = 0; k0 < FIN; k0 += KC) {
        // stage A: 128 rows x 32 cols fp32 -> fp16 (+relu)
        for (int i = t; i < 128 * 8; i += 256) {
            int r = i >> 3, c4 = i & 7;
            int n = rowblk + r;
            float4 v = make_float4(0.f, 0.f, 0.f, 0.f);
            if (n < N)
                v = *(const float4*)(in + (size_t)n * FIN + k0 + c4 * 4);
            if (RELU) {
                v.x = fmaxf(v.x, 0.f); v.y = fmaxf(v.y, 0.f);
                v.z = fmaxf(v.z, 0.f); v.w = fmaxf(v.w, 0.f);
            }
            __half2* dp = (__half2*)&As[r * LDA + c4 * 4];
            dp[0] = __floats2half2_rn(v.x, v.y);
            dp[1] = __floats2half2_rn(v.z, v.w);
        }
        // stage B: KC x FOUTP (zero-pad cols >= FOUT)
        for (int i = t; i < KC * LDB; i += 256) {
            int r = i / LDB, c = i % LDB;
            __half hv = __float2half(0.f);
            if (c < FOUT) hv = Wh[(size_t)(k0 + r) * FOUT + c];
            Bs[r * LDB + c] = hv;
        }
        __syncthreads();

#pragma unroll
        for (int ks = 0; ks < KC / 16; ks++) {
            unsigned a[2][4];
#pragma unroll
            for (int mt = 0; mt < 2; mt++) {
                int row = wm * 32 + mt * 16 + (lane & 15);
                int col = ks * 16 + (lane >> 4) * 8;
                ldsm_x4(a[mt], smem_u32(&As[row * LDA + col]));
            }
            unsigned b[NT][2];
#pragma unroll
            for (int np = 0; np < NT / 2; np++) {
                int row = ks * 16 + (lane & 15);
                int col = wn * (NT * 8) + np * 16 + (lane >> 4) * 8;
                unsigned r4[4];
                ldsm_x4t(r4, smem_u32(&Bs[row * LDB + col]));
                b[2 * np][0]     = r4[0]; b[2 * np][1]     = r4[1];
                b[2 * np + 1][0] = r4[2]; b[2 * np + 1][1] = r4[3];
            }
#pragma unroll
            for (int mt = 0; mt < 2; mt++)
#pragma unroll
                for (int nt = 0; nt < NT; nt++)
                    mma16816(acc[mt][nt], a[mt], b[nt]);
        }
        __syncthreads();
    }

    // epilogue: scale by dis[row], store fp16 pairs
#pragma unroll
    for (int mt = 0; mt < 2; mt++) {
        int r_lo = rowblk + wm * 32 + mt * 16 + (lane >> 2);
        int r_hi = r_lo + 8;
        float dl = (r_lo < N) ? g_dis[r_lo] : 0.f;
        float dh = (r_hi < N) ? g_dis[r_hi] : 0.f;
#pragma unroll
        for (int nt = 0; nt < NT; nt++) {
            int c = wn * (NT * 8) + nt * 8 + (lane & 3) * 2;
            if (r_lo < N)
                *(__half2*)&xw[(size_t)r_lo * FOUTP + c] =
                    __floats2half2_rn(dl * acc[mt][nt][0], dl * acc[mt][nt][1]);
            if (r_hi < N)
                *(__half2*)&xw[(size_t)r_hi * FOUTP + c] =
                    __floats2half2_rn(dh * acc[mt][nt][2], dh * acc[mt][nt][3]);
        }
    }
}

// ---------------------------------------------------------------------------
// 8) Pull aggregation, 8-edge batched MLP:
//    out[n] = dis[n] * ( sum_e |w_e| * xw'[col] + xw'[n] ) + b
// ---------------------------------------------------------------------------
template<int FOUT, int XWS, int NF>
__global__ __launch_bounds__(256) void gather_kernel(
    const __half* __restrict__ xw, const float* __restrict__ b,
    float* __restrict__ out, int N)
{
    const int lane = threadIdx.x & 31;
    const int n = (blockIdx.x * blockDim.x + threadIdx.x) >> 5;
    if (n >= N) return;

    const int beg = g_rowptr[n];
    const int end = g_rowptr[n + 1];

    float acc[NF];
#pragma unroll
    for (int j = 0; j < NF; j++) acc[j] = 0.0f;

    for (int e0 = beg; e0 < end; e0 += 32) {
        const int cnt = min(end - e0, 32);
        int2 cv = make_int2(0, 0);
        if (lane < cnt) cv = g_csr[e0 + lane];

        for (int k = 0; k < cnt; k += 8) {
            unsigned off[8];
            float    val[8];
#pragma unroll
            for (int i = 0; i < 8; i++) {
                int kk = k + i;
                int src = __shfl_sync(0xffffffffu, cv.x, kk & 31);
                float v = __int_as_float(__shfl_sync(0xffffffffu, cv.y, kk & 31));
                off[i] = (unsigned)src * XWS;
                val[i] = (kk < cnt) ? v : 0.0f;
            }
            __half hv[8][NF];
#pragma unroll
            for (int i = 0; i < 8; i++)
#pragma unroll
                for (int j = 0; j < NF; j++)
                    hv[i][j] = __ldg(&xw[off[i] + lane + 32 * j]);
#pragma unroll
            for (int i = 0; i < 8; i++)
#pragma unroll
                for (int j = 0; j < NF; j++)
                    acc[j] += val[i] * __half2float(hv[i][j]);
        }
    }

    const float d = g_dis[n];
    const __half* xr = xw + (size_t)n * XWS;
#pragma unroll
    for (int j = 0; j < NF; j++) {
        const int f = lane + 32 * j;
        if (f < FOUT)
            out[(size_t)n * FOUT + f] =
                d * (acc[j] + __half2float(xr[f])) + b[f];
    }
}

// ---------------------------------------------------------------------------
// 9) mean pool (+relu)  10) classifier + softmax
// ---------------------------------------------------------------------------
__global__ void pool_kernel(const float* __restrict__ h, int N) {
    int tid = blockIdx.x * blockDim.x + threadIdx.x;
    int n = tid >> 5;
    int f = tid & 31;
    if (n >= N) return;
    int g = g_bat[n];
    if (f < F3)       atomicAdd(&g_pool[g * F3 + f], fmaxf(h[n * F3 + f], 0.0f));
    else if (f == 31) atomicAdd(&g_cnt[g], 1.0f);
}

__global__ void final_kernel(const float* __restrict__ Wf,
                             const float* __restrict__ bf,
                             float* __restrict__ out) {
    int g = threadIdx.x;
    if (g >= G_MAX) return;
    float cnt = fmaxf(g_cnt[g], 1.0f);
    float p[F3];
#pragma unroll
    for (int j = 0; j < F3; j++) p[j] = g_pool[g * F3 + j] / cnt;
    float lo[NCLS];
    float m = -1e30f;
#pragma unroll
    for (int k = 0; k < NCLS; k++) {
        float s = bf[k];
#pragma unroll
        for (int j = 0; j < F3; j++) s += p[j] * Wf[j * NCLS + k];
        lo[k] = s;
        m = fmaxf(m, s);
    }
    float sum = 0.0f;
#pragma unroll
    for (int k = 0; k < NCLS; k++) { lo[k] = expf(lo[k] - m); sum += lo[k]; }
    float inv = 1.0f / sum;
#pragma unroll
    for (int k = 0; k < NCLS; k++) out[g * NCLS + k] = lo[k] * inv;
}

// ---------------------------------------------------------------------------
// Launch
// ---------------------------------------------------------------------------
extern "C" void kernel_launch(void* const* d_in, const int* in_sizes, int n_in,
                              void* d_out, int out_size) {
    const float* x   = (const float*)d_in[0];
    const void*  ei  = d_in[1];
    const float* ew  = (const float*)d_in[2];
    const void*  bat = d_in[3];
    const float* W1  = (const float*)d_in[4];
    const float* b1  = (const float*)d_in[5];
    const float* W2  = (const float*)d_in[6];
    const float* b2  = (const float*)d_in[7];
    const float* W3  = (const float*)d_in[8];
    const float* b3  = (const float*)d_in[9];
    const float* Wf  = (const float*)d_in[10];
    const float* bf  = (const float*)d_in[11];
    float* out = (float*)d_out;

    const int E = in_sizes[2];
    const int N = in_sizes[3];

    __half *pXW, *pWh;
    float *pB, *pC;
    cudaGetSymbolAddress((void**)&pXW, g_xw);
    cudaGetSymbolAddress((void**)&pWh, g_wh);
    cudaGetSymbolAddress((void**)&pB,  g_bufB);
    cudaGetSymbolAddress((void**)&pC,  g_bufC);

    const int TB = 256;
    const int gE = (E + TB - 1) / TB;
    const int gN = (N + TB - 1) / TB;
    const int gGemm = (N + 127) / 128;
    const int gWarpN = (N * 32 + TB - 1) / TB;

    detect_kernel<<<1, 256>>>((const unsigned*)ei);
    zero_kernel<<<gN, TB>>>(N);
    convert_hist_kernel<<<gE, TB>>>(ei, bat, E, N);
    wconv_kernel<<<(WTOT + TB - 1) / TB, TB>>>(W1, W2, W3);
    scan_kernel<<<1, 1024>>>(N);
    place_kernel<<<gE, TB>>>(ew, E);
    degdis_kernel<<<gWarpN, TB>>>(N);

    // Layer 1: 128 -> 96
    gemm_hmma<128, 96, 96, false><<<gGemm, TB>>>(x, pWh + WOFF1, pXW, N);
    gather_kernel<96, 96, 3><<<gWarpN, TB>>>(pXW, b1, pB, N);

    // Layer 2: 96 -> 96
    gemm_hmma<96, 96, 96, true><<<gGemm, TB>>>(pB, pWh + WOFF2, pXW, N);
    gather_kernel<96, 96, 3><<<gWarpN, TB>>>(pXW, b2, pC, N);

    // Layer 3: 96 -> 30 (xw padded to stride 32)
    gemm_hmma<96, 30, 32, true><<<gGemm, TB>>>(pC, pWh + WOFF3, pXW, N);
    gather_kernel<30, 32, 1><<<gWarpN, TB>>>(pXW, b3, pB, N);

    pool_kernel<<<gWarpN, TB>>>(pB, N);
    final_kernel<<<1, 256>>>(Wf, bf, out);

    (void)n_in; (void)out_size;
}